// round 1
// baseline (speedup 1.0000x reference)
#include <cuda_runtime.h>
#include <cuda_bf16.h>

// ---------------------------------------------------------------------------
// IntentSlotLabellingModel: emb-gather -> GEMM1+ReLU -> GEMM2+ReLU -> GEMM3+bias
// Shapes: M=32768 tokens, E=512, C=512, H=1024, L=128.
// Round-0 baseline: fp32 register-blocked SGEMM (BM=BN=128, BK=8, 8x8/thread),
// fused gather / bias / relu. Intermediates in __device__ scratch (no allocs).
// ---------------------------------------------------------------------------

#define BM 128
#define BN 128
#define BK 8
#define TM 8
#define TN 8

// Scratch activations (allowed: __device__ globals, no runtime allocation)
__device__ float g_H[32768L * 512];    // post-conv relu activations
__device__ float g_Z[32768L * 1024];   // post-dec_w1 relu activations

// GATHER : A row index comes from tokens[] (A = emb_table)
// BTRANS : B global layout is [N, K] row-major (conv_w), else [K, N] row-major
// RELU   : apply relu in epilogue
template <bool GATHER, bool BTRANS, bool RELU>
__global__ void __launch_bounds__(256, 2)
fused_gemm_kernel(const float* __restrict__ A,
                  const float* __restrict__ B,
                  const float* __restrict__ bias,
                  float* __restrict__ C,
                  const int* __restrict__ tokens,
                  int M, int N, int K)
{
    __shared__ float As[BK][BM];
    __shared__ float Bs[BK][BN];

    const int n0 = blockIdx.x * BN;
    const int m0 = blockIdx.y * BM;
    const int tid = threadIdx.x;

    // ---- A tile load mapping: 128 rows x 8 k, one float4 per thread ----
    const int a_row = tid >> 1;          // 0..127
    const int a_kv  = (tid & 1) * 4;     // 0 or 4
    long a_row_g;
    if (GATHER)
        a_row_g = (long)tokens[m0 + a_row];
    else
        a_row_g = (long)(m0 + a_row);
    const float* a_ptr = A + a_row_g * (long)K + a_kv;

    // ---- B tile load mapping ----
    const float* b_ptr;
    int b_r, b_c;
    if (BTRANS) {
        // B global [N, K]: Bs[k][n] = Bg[n][k]; one float4 along k per thread
        b_r = tid >> 1;                  // local n, 0..127
        b_c = (tid & 1) * 4;             // k offset, 0 or 4
        b_ptr = B + (long)(n0 + b_r) * (long)K + b_c;
    } else {
        // B global [K, N]: contiguous n; one float4 along n per thread
        b_r = tid >> 5;                  // k, 0..7
        b_c = (tid & 31) * 4;            // local n
        b_ptr = B + (long)b_r * (long)N + n0 + b_c;
    }

    const int tx = tid & 15;             // 16 thread cols
    const int ty = tid >> 4;             // 16 thread rows

    float acc[TM][TN];
    #pragma unroll
    for (int i = 0; i < TM; i++)
        #pragma unroll
        for (int j = 0; j < TN; j++)
            acc[i][j] = 0.0f;

    for (int k0 = 0; k0 < K; k0 += BK) {
        // load A tile (transposed into As[k][m])
        float4 av = *reinterpret_cast<const float4*>(a_ptr + k0);
        As[a_kv + 0][a_row] = av.x;
        As[a_kv + 1][a_row] = av.y;
        As[a_kv + 2][a_row] = av.z;
        As[a_kv + 3][a_row] = av.w;

        // load B tile into Bs[k][n]
        if (BTRANS) {
            float4 bv = *reinterpret_cast<const float4*>(b_ptr + k0);
            Bs[b_c + 0][b_r] = bv.x;
            Bs[b_c + 1][b_r] = bv.y;
            Bs[b_c + 2][b_r] = bv.z;
            Bs[b_c + 3][b_r] = bv.w;
        } else {
            float4 bv = *reinterpret_cast<const float4*>(b_ptr + (long)k0 * N);
            *reinterpret_cast<float4*>(&Bs[b_r][b_c]) = bv;
        }
        __syncthreads();

        #pragma unroll
        for (int k = 0; k < BK; k++) {
            float a_reg[TM], b_reg[TN];
            // vectorized smem reads (8 consecutive floats each)
            float4 a0 = *reinterpret_cast<const float4*>(&As[k][ty * TM]);
            float4 a1 = *reinterpret_cast<const float4*>(&As[k][ty * TM + 4]);
            float4 bv0 = *reinterpret_cast<const float4*>(&Bs[k][tx * TN]);
            float4 bv1 = *reinterpret_cast<const float4*>(&Bs[k][tx * TN + 4]);
            a_reg[0] = a0.x; a_reg[1] = a0.y; a_reg[2] = a0.z; a_reg[3] = a0.w;
            a_reg[4] = a1.x; a_reg[5] = a1.y; a_reg[6] = a1.z; a_reg[7] = a1.w;
            b_reg[0] = bv0.x; b_reg[1] = bv0.y; b_reg[2] = bv0.z; b_reg[3] = bv0.w;
            b_reg[4] = bv1.x; b_reg[5] = bv1.y; b_reg[6] = bv1.z; b_reg[7] = bv1.w;

            #pragma unroll
            for (int i = 0; i < TM; i++)
                #pragma unroll
                for (int j = 0; j < TN; j++)
                    acc[i][j] = fmaf(a_reg[i], b_reg[j], acc[i][j]);
        }
        __syncthreads();
    }

    // ---- epilogue: bias (+relu), vectorized stores ----
    float bb[TN];
    #pragma unroll
    for (int j = 0; j < TN; j++)
        bb[j] = bias[n0 + tx * TN + j];

    #pragma unroll
    for (int i = 0; i < TM; i++) {
        long row = (long)m0 + ty * TM + i;
        float* crow = C + row * (long)N + n0 + tx * TN;
        #pragma unroll
        for (int j4 = 0; j4 < TN; j4 += 4) {
            float4 v;
            v.x = acc[i][j4 + 0] + bb[j4 + 0];
            v.y = acc[i][j4 + 1] + bb[j4 + 1];
            v.z = acc[i][j4 + 2] + bb[j4 + 2];
            v.w = acc[i][j4 + 3] + bb[j4 + 3];
            if (RELU) {
                v.x = fmaxf(v.x, 0.0f);
                v.y = fmaxf(v.y, 0.0f);
                v.z = fmaxf(v.z, 0.0f);
                v.w = fmaxf(v.w, 0.0f);
            }
            *reinterpret_cast<float4*>(crow + j4) = v;
        }
    }
}

extern "C" void kernel_launch(void* const* d_in, const int* in_sizes, int n_in,
                              void* d_out, int out_size)
{
    const int*   tokens = (const int*)  d_in[0];   // [B*S] int32
    const float* emb    = (const float*)d_in[1];   // [VOCAB, 512]
    const float* conv_w = (const float*)d_in[2];   // [512, 512]  (N,K)
    const float* conv_b = (const float*)d_in[3];   // [512]
    const float* w1     = (const float*)d_in[4];   // [512, 1024] (K,N)
    const float* b1     = (const float*)d_in[5];   // [1024]
    const float* w2     = (const float*)d_in[6];   // [1024, 128] (K,N)
    const float* b2     = (const float*)d_in[7];   // [128]
    float* out = (float*)d_out;                    // [M, 128]

    const int M = in_sizes[0];                     // 32768
    const int E = 512, Cc = 512, Hd = 1024, L = 128;

    float *H = nullptr, *Z = nullptr;
    cudaGetSymbolAddress((void**)&H, g_H);
    cudaGetSymbolAddress((void**)&Z, g_Z);

    dim3 block(256);

    // L1: H = relu(gather(emb, tokens) @ conv_w^T + conv_b)   [M, 512]
    fused_gemm_kernel<true, true, true>
        <<<dim3(Cc / BN, M / BM), block>>>(emb, conv_w, conv_b, H, tokens, M, Cc, E);

    // L2: Z = relu(H @ dec_w1 + dec_b1)                       [M, 1024]
    fused_gemm_kernel<false, false, true>
        <<<dim3(Hd / BN, M / BM), block>>>(H, w1, b1, Z, nullptr, M, Hd, Cc);

    // L3: out = Z @ dec_w2 + dec_b2                           [M, 128]
    fused_gemm_kernel<false, false, false>
        <<<dim3(L / BN, M / BM), block>>>(Z, w2, b2, out, nullptr, M, L, Hd);
}

// round 2
// speedup vs baseline: 2.6294x; 2.6294x over previous
#include <cuda_runtime.h>
#include <cuda_bf16.h>
#include <cstdint>

// ---------------------------------------------------------------------------
// IntentSlotLabellingModel: gather -> GEMM1+ReLU -> GEMM2+ReLU -> GEMM3+bias
// M=32768, E=512, C=512, H=1024, L=128.
// Round 1: TF32 warp-MMA (mma.sync.m16n8k8) tensor-core GEMM.
//   Block 256 thr = 8 warps (2x4), tile 128x128x16, warp tile 64x32.
//   Smem As[m][k] / Bs[n][k] with pad 4 -> conflict-free frag LDS.
// ---------------------------------------------------------------------------

#define BM 128
#define BN 128
#define BK 16
#define PAD 4
#define STRIDE (BK + PAD)   // 20 floats per row

__device__ float g_H[32768L * 512];    // post-conv relu activations
__device__ float g_Z[32768L * 1024];   // post-dec_w1 relu activations

__device__ __forceinline__ uint32_t f2tf32(float x) {
    uint32_t r;
    asm("cvt.rna.tf32.f32 %0, %1;" : "=r"(r) : "f"(x));
    return r;
}

__device__ __forceinline__ void mma_tf32(float* d, const uint32_t* a, const uint32_t* b) {
    asm volatile(
        "mma.sync.aligned.m16n8k8.row.col.f32.tf32.tf32.f32 "
        "{%0,%1,%2,%3}, {%4,%5,%6,%7}, {%8,%9}, {%0,%1,%2,%3};"
        : "+f"(d[0]), "+f"(d[1]), "+f"(d[2]), "+f"(d[3])
        : "r"(a[0]), "r"(a[1]), "r"(a[2]), "r"(a[3]), "r"(b[0]), "r"(b[1]));
}

// GATHER : A row index from tokens[] (A = emb_table)
// BTRANS : B global layout is [N, K] row-major (conv_w), else [K, N]
// RELU   : relu in epilogue
template <bool GATHER, bool BTRANS, bool RELU>
__global__ void __launch_bounds__(256, 2)
mma_gemm_kernel(const float* __restrict__ A,
                const float* __restrict__ B,
                const float* __restrict__ bias,
                float* __restrict__ C,
                const int* __restrict__ tokens,
                int M, int N, int K)
{
    __shared__ float As[BM][STRIDE];
    __shared__ float Bs[BN][STRIDE];

    const int n0 = blockIdx.x * BN;
    const int m0 = blockIdx.y * BM;
    const int tid  = threadIdx.x;
    const int lane = tid & 31;
    const int warp = tid >> 5;
    const int warp_m = (warp >> 2) * 64;   // 0 or 64
    const int warp_n = (warp & 3) * 32;    // 0,32,64,96

    // ---- A gmem mapping: 128 rows x 16k, float4 per task, 2 tasks/thread ----
    const float* aptr[2];
    int ar[2], ac4[2];
    #pragma unroll
    for (int i = 0; i < 2; i++) {
        int idx = tid + i * 256;
        ar[i]  = idx >> 2;            // 0..127
        ac4[i] = (idx & 3) * 4;       // 0,4,8,12
        long rg = GATHER ? (long)tokens[m0 + ar[i]] : (long)(m0 + ar[i]);
        aptr[i] = A + rg * (long)K + ac4[i];
    }

    // ---- B gmem mapping ----
    const float* bptr[2];
    int br[2], bc4[2];     // BTRANS path: local n, k-quad offset
    int bn_[2], bkq[2];    // non-trans path
    if (BTRANS) {
        #pragma unroll
        for (int i = 0; i < 2; i++) {
            int idx = tid + i * 256;
            br[i]  = idx >> 2;
            bc4[i] = (idx & 3) * 4;
            bptr[i] = B + (long)(n0 + br[i]) * (long)K + bc4[i];
        }
    } else {
        #pragma unroll
        for (int i = 0; i < 2; i++) {
            int idx = tid + i * 256;
            bn_[i] = idx & 127;       // local n
            bkq[i] = idx >> 7;        // 0..3  k-quad
            bptr[i] = B + (long)n0 + bn_[i];
        }
    }

    float acc[4][4][4];
    #pragma unroll
    for (int mt = 0; mt < 4; mt++)
        #pragma unroll
        for (int nt = 0; nt < 4; nt++)
            #pragma unroll
            for (int r = 0; r < 4; r++)
                acc[mt][nt][r] = 0.0f;

    const int gr = lane >> 2;    // 0..7
    const int gc = lane & 3;     // 0..3

    for (int k0 = 0; k0 < K; k0 += BK) {
        // ---- load A tile ----
        #pragma unroll
        for (int i = 0; i < 2; i++) {
            float4 v = *reinterpret_cast<const float4*>(aptr[i] + k0);
            float4 t;
            t.x = __uint_as_float(f2tf32(v.x));
            t.y = __uint_as_float(f2tf32(v.y));
            t.z = __uint_as_float(f2tf32(v.z));
            t.w = __uint_as_float(f2tf32(v.w));
            *reinterpret_cast<float4*>(&As[ar[i]][ac4[i]]) = t;
        }
        // ---- load B tile ----
        if (BTRANS) {
            #pragma unroll
            for (int i = 0; i < 2; i++) {
                float4 v = *reinterpret_cast<const float4*>(bptr[i] + k0);
                float4 t;
                t.x = __uint_as_float(f2tf32(v.x));
                t.y = __uint_as_float(f2tf32(v.y));
                t.z = __uint_as_float(f2tf32(v.z));
                t.w = __uint_as_float(f2tf32(v.w));
                *reinterpret_cast<float4*>(&Bs[br[i]][bc4[i]]) = t;
            }
        } else {
            #pragma unroll
            for (int i = 0; i < 2; i++) {
                float4 t;
                const float* bp = bptr[i] + (long)(k0 + bkq[i] * 4) * (long)N;
                t.x = __uint_as_float(f2tf32(bp[0]));
                t.y = __uint_as_float(f2tf32(bp[(long)N]));
                t.z = __uint_as_float(f2tf32(bp[2L * N]));
                t.w = __uint_as_float(f2tf32(bp[3L * N]));
                *reinterpret_cast<float4*>(&Bs[bn_[i]][bkq[i] * 4]) = t;
            }
        }
        __syncthreads();

        // ---- compute: 2 k-steps of 8 ----
        #pragma unroll
        for (int ks = 0; ks < BK; ks += 8) {
            uint32_t af[4][4], bf[4][2];
            #pragma unroll
            for (int mt = 0; mt < 4; mt++) {
                int r = warp_m + mt * 16 + gr;
                int c = ks + gc;
                af[mt][0] = __float_as_uint(As[r][c]);
                af[mt][1] = __float_as_uint(As[r + 8][c]);
                af[mt][2] = __float_as_uint(As[r][c + 4]);
                af[mt][3] = __float_as_uint(As[r + 8][c + 4]);
            }
            #pragma unroll
            for (int nt = 0; nt < 4; nt++) {
                int n = warp_n + nt * 8 + gr;
                int c = ks + gc;
                bf[nt][0] = __float_as_uint(Bs[n][c]);
                bf[nt][1] = __float_as_uint(Bs[n][c + 4]);
            }
            #pragma unroll
            for (int mt = 0; mt < 4; mt++)
                #pragma unroll
                for (int nt = 0; nt < 4; nt++)
                    mma_tf32(acc[mt][nt], af[mt], bf[nt]);
        }
        __syncthreads();
    }

    // ---- epilogue: bias (+relu), float2 stores ----
    #pragma unroll
    for (int nt = 0; nt < 4; nt++) {
        int n = n0 + warp_n + nt * 8 + gc * 2;
        float bb0 = bias[n], bb1 = bias[n + 1];
        #pragma unroll
        for (int mt = 0; mt < 4; mt++) {
            long m = (long)m0 + warp_m + mt * 16 + gr;
            float2 v0, v1;
            v0.x = acc[mt][nt][0] + bb0;
            v0.y = acc[mt][nt][1] + bb1;
            v1.x = acc[mt][nt][2] + bb0;
            v1.y = acc[mt][nt][3] + bb1;
            if (RELU) {
                v0.x = fmaxf(v0.x, 0.0f); v0.y = fmaxf(v0.y, 0.0f);
                v1.x = fmaxf(v1.x, 0.0f); v1.y = fmaxf(v1.y, 0.0f);
            }
            *reinterpret_cast<float2*>(C + m * (long)N + n) = v0;
            *reinterpret_cast<float2*>(C + (m + 8) * (long)N + n) = v1;
        }
    }
}

extern "C" void kernel_launch(void* const* d_in, const int* in_sizes, int n_in,
                              void* d_out, int out_size)
{
    const int*   tokens = (const int*)  d_in[0];   // [B*S] int32
    const float* emb    = (const float*)d_in[1];   // [VOCAB, 512]
    const float* conv_w = (const float*)d_in[2];   // [512, 512]  (N,K)
    const float* conv_b = (const float*)d_in[3];   // [512]
    const float* w1     = (const float*)d_in[4];   // [512, 1024] (K,N)
    const float* b1     = (const float*)d_in[5];   // [1024]
    const float* w2     = (const float*)d_in[6];   // [1024, 128] (K,N)
    const float* b2     = (const float*)d_in[7];   // [128]
    float* out = (float*)d_out;                    // [M, 128]

    const int M = in_sizes[0];                     // 32768
    const int E = 512, Cc = 512, Hd = 1024, L = 128;

    float *H = nullptr, *Z = nullptr;
    cudaGetSymbolAddress((void**)&H, g_H);
    cudaGetSymbolAddress((void**)&Z, g_Z);

    dim3 block(256);

    // L1: H = relu(gather(emb, tokens) @ conv_w^T + conv_b)   [M, 512]
    mma_gemm_kernel<true, true, true>
        <<<dim3(Cc / BN, M / BM), block>>>(emb, conv_w, conv_b, H, tokens, M, Cc, E);

    // L2: Z = relu(H @ dec_w1 + dec_b1)                       [M, 1024]
    mma_gemm_kernel<false, false, true>
        <<<dim3(Hd / BN, M / BM), block>>>(H, w1, b1, Z, nullptr, M, Hd, Cc);

    // L3: out = Z @ dec_w2 + dec_b2                           [M, 128]
    mma_gemm_kernel<false, false, false>
        <<<dim3(L / BN, M / BM), block>>>(Z, w2, b2, out, nullptr, M, L, Hd);
}

// round 4
// speedup vs baseline: 2.8677x; 1.0906x over previous
#include <cuda_runtime.h>
#include <cuda_bf16.h>
#include <cstdint>

// ---------------------------------------------------------------------------
// IntentSlotLabellingModel on GB300 (sm_103a), Round 3:
// TF32 mma.sync.m16n8k8 GEMM chain (tcgen05 is PTX-gated off in this harness).
//   gather -> GEMM1+ReLU -> GEMM2+ReLU -> GEMM3+bias
//   M=32768, E=512, C=512, H=1024, L=128.
// CTA tile 256x128, 8 warps (4m x 2n), warp tile 64x64 (1.0 LDS per MMA),
// BK=16, double-buffered smem + register-prefetch pipeline, producer-side
// cvt.rna tf32 conversion. All B operands pre-transposed to [N,K].
// ---------------------------------------------------------------------------

#define BM 256
#define BN 128
#define BK 16
#define SSTR 20                   // smem row stride in floats (BK + 4 pad)
#define A_FL (BM * SSTR)          // 5120 floats per A stage
#define B_FL (BN * SSTR)          // 2560 floats per B stage
#define STG_FL (A_FL + B_FL)      // 7680 floats per stage

__device__ float g_H[32768L * 512];     // post-conv relu
__device__ float g_Z[32768L * 1024];    // post-dec1 relu
__device__ float g_w1t[1024L * 512];    // dec_w1 -> [N,K]
__device__ float g_w2t[128L * 1024];    // dec_w2 -> [N,K]

__device__ __forceinline__ float f2tf32(float x) {
    uint32_t r;
    asm("cvt.rna.tf32.f32 %0, %1;" : "=r"(r) : "f"(x));
    return __uint_as_float(r);
}
__device__ __forceinline__ void mma_tf32(float* d, const uint32_t* a, const uint32_t* b) {
    asm volatile(
        "mma.sync.aligned.m16n8k8.row.col.f32.tf32.tf32.f32 "
        "{%0,%1,%2,%3}, {%4,%5,%6,%7}, {%8,%9}, {%0,%1,%2,%3};"
        : "+f"(d[0]), "+f"(d[1]), "+f"(d[2]), "+f"(d[3])
        : "r"(a[0]), "r"(a[1]), "r"(a[2]), "r"(a[3]), "r"(b[0]), "r"(b[1]));
}

template <bool GATHER>
__global__ void __launch_bounds__(256, 1)
mma_gemm(const float* __restrict__ A,       // [M or VOCAB, K]
         const float* __restrict__ B,       // [N, K]
         const float* __restrict__ bias,    // [N]
         float* __restrict__ C,             // [M, N]
         const int* __restrict__ tokens,
         int N, int K, int relu)
{
    extern __shared__ float smem[];

    const int tid  = threadIdx.x;
    const int lane = tid & 31;
    const int warp = tid >> 5;
    const int warp_m = (warp >> 1) * 64;     // 0,64,128,192
    const int warp_n = (warp & 1) * 64;      // 0,64
    const int gr = lane >> 2;                // 0..7
    const int gc = lane & 3;                 // 0..3

    const int  n0 = blockIdx.x * BN;
    const long m0 = (long)blockIdx.y * BM;

    // ---- gmem->smem task mapping (rows fixed across stages) ----
    const float* aptr[4];  int asoff[4];
    #pragma unroll
    for (int i = 0; i < 4; i++) {
        int idx = tid + i * 256;             // 0..1023
        int r   = idx >> 2;                  // 0..255
        int c4  = (idx & 3) * 4;             // 0,4,8,12
        long rg = GATHER ? (long)tokens[m0 + r] : (m0 + r);
        aptr[i]  = A + rg * (long)K + c4;
        asoff[i] = r * SSTR + c4;
    }
    const float* bptr[2];  int bsoff[2];
    #pragma unroll
    for (int i = 0; i < 2; i++) {
        int idx = tid + i * 256;             // 0..511
        int r   = idx >> 2;                  // 0..127
        int c4  = (idx & 3) * 4;
        bptr[i]  = B + (long)(n0 + r) * (long)K + c4;
        bsoff[i] = r * SSTR + c4;
    }

    float acc[4][8][4];
    #pragma unroll
    for (int mt = 0; mt < 4; mt++)
        #pragma unroll
        for (int nt = 0; nt < 8; nt++)
            #pragma unroll
            for (int r = 0; r < 4; r++)
                acc[mt][nt][r] = 0.0f;

    const int S = K / BK;
    float4 ra[4], rb[2];

    // preload stage 0 into registers, then smem buf 0
    #pragma unroll
    for (int i = 0; i < 4; i++) ra[i] = *reinterpret_cast<const float4*>(aptr[i]);
    #pragma unroll
    for (int i = 0; i < 2; i++) rb[i] = *reinterpret_cast<const float4*>(bptr[i]);
    {
        float* As = smem;  float* Bs = smem + A_FL;
        #pragma unroll
        for (int i = 0; i < 4; i++) {
            float4 t; t.x = f2tf32(ra[i].x); t.y = f2tf32(ra[i].y);
            t.z = f2tf32(ra[i].z); t.w = f2tf32(ra[i].w);
            *reinterpret_cast<float4*>(As + asoff[i]) = t;
        }
        #pragma unroll
        for (int i = 0; i < 2; i++) {
            float4 t; t.x = f2tf32(rb[i].x); t.y = f2tf32(rb[i].y);
            t.z = f2tf32(rb[i].z); t.w = f2tf32(rb[i].w);
            *reinterpret_cast<float4*>(Bs + bsoff[i]) = t;
        }
    }

    for (int s = 0; s < S; s++) {
        __syncthreads();                      // stage s buffer ready
        const int p = s & 1;
        const float* As = smem + p * STG_FL;
        const float* Bs = smem + p * STG_FL + A_FL;

        // issue next-stage global loads early (latency hidden by compute)
        if (s + 1 < S) {
            const int k0 = (s + 1) * BK;
            #pragma unroll
            for (int i = 0; i < 4; i++)
                ra[i] = *reinterpret_cast<const float4*>(aptr[i] + k0);
            #pragma unroll
            for (int i = 0; i < 2; i++)
                rb[i] = *reinterpret_cast<const float4*>(bptr[i] + k0);
        }

        // ---- compute: 2 x k8 ----
        #pragma unroll
        for (int ks = 0; ks < BK; ks += 8) {
            uint32_t af[4][4], bf[8][2];
            #pragma unroll
            for (int mt = 0; mt < 4; mt++) {
                int r = (warp_m + mt * 16 + gr) * SSTR + ks + gc;
                af[mt][0] = __float_as_uint(As[r]);
                af[mt][1] = __float_as_uint(As[r + 8 * SSTR]);
                af[mt][2] = __float_as_uint(As[r + 4]);
                af[mt][3] = __float_as_uint(As[r + 8 * SSTR + 4]);
            }
            #pragma unroll
            for (int nt = 0; nt < 8; nt++) {
                int r = (warp_n + nt * 8 + gr) * SSTR + ks + gc;
                bf[nt][0] = __float_as_uint(Bs[r]);
                bf[nt][1] = __float_as_uint(Bs[r + 4]);
            }
            #pragma unroll
            for (int mt = 0; mt < 4; mt++)
                #pragma unroll
                for (int nt = 0; nt < 8; nt++)
                    mma_tf32(acc[mt][nt], af[mt], bf[nt]);
        }

        // store prefetched stage into the other buffer (no races: other buf)
        if (s + 1 < S) {
            float* An = smem + (1 - p) * STG_FL;
            float* Bn = smem + (1 - p) * STG_FL + A_FL;
            #pragma unroll
            for (int i = 0; i < 4; i++) {
                float4 t; t.x = f2tf32(ra[i].x); t.y = f2tf32(ra[i].y);
                t.z = f2tf32(ra[i].z); t.w = f2tf32(ra[i].w);
                *reinterpret_cast<float4*>(An + asoff[i]) = t;
            }
            #pragma unroll
            for (int i = 0; i < 2; i++) {
                float4 t; t.x = f2tf32(rb[i].x); t.y = f2tf32(rb[i].y);
                t.z = f2tf32(rb[i].z); t.w = f2tf32(rb[i].w);
                *reinterpret_cast<float4*>(Bn + bsoff[i]) = t;
            }
        }
    }

    // ---- epilogue: bias (+relu), float2 stores ----
    #pragma unroll
    for (int nt = 0; nt < 8; nt++) {
        int n = n0 + warp_n + nt * 8 + gc * 2;
        float bb0 = bias[n], bb1 = bias[n + 1];
        #pragma unroll
        for (int mt = 0; mt < 4; mt++) {
            long m = m0 + warp_m + mt * 16 + gr;
            float2 v0, v1;
            v0.x = acc[mt][nt][0] + bb0;  v0.y = acc[mt][nt][1] + bb1;
            v1.x = acc[mt][nt][2] + bb0;  v1.y = acc[mt][nt][3] + bb1;
            if (relu) {
                v0.x = fmaxf(v0.x, 0.0f); v0.y = fmaxf(v0.y, 0.0f);
                v1.x = fmaxf(v1.x, 0.0f); v1.y = fmaxf(v1.y, 0.0f);
            }
            *reinterpret_cast<float2*>(C + m * (long)N + n)       = v0;
            *reinterpret_cast<float2*>(C + (m + 8) * (long)N + n) = v1;
        }
    }
}

// ---------------------------------------------------------------------------
// Weight transpose: in [K,N] row-major -> out [N,K] row-major
// ---------------------------------------------------------------------------
__global__ void transpose_k(const float* __restrict__ in, float* __restrict__ out,
                            int K, int N)
{
    __shared__ float t[32][33];
    int n0 = blockIdx.x * 32, k0 = blockIdx.y * 32;
    int x = threadIdx.x, y = threadIdx.y;
    #pragma unroll
    for (int i = 0; i < 32; i += 8)
        t[y + i][x] = in[(long)(k0 + y + i) * N + n0 + x];
    __syncthreads();
    #pragma unroll
    for (int i = 0; i < 32; i += 8)
        out[(long)(n0 + y + i) * K + k0 + x] = t[x][y + i];
}

extern "C" void kernel_launch(void* const* d_in, const int* in_sizes, int n_in,
                              void* d_out, int out_size)
{
    const int*   tokens = (const int*)  d_in[0];   // [32768]
    const float* emb    = (const float*)d_in[1];   // [VOCAB, 512]
    const float* conv_w = (const float*)d_in[2];   // [512, 512]  (N,K) already
    const float* conv_b = (const float*)d_in[3];   // [512]
    const float* w1     = (const float*)d_in[4];   // [512, 1024] (K,N)
    const float* b1     = (const float*)d_in[5];   // [1024]
    const float* w2     = (const float*)d_in[6];   // [1024, 128] (K,N)
    const float* b2     = (const float*)d_in[7];   // [128]
    float* out = (float*)d_out;                    // [32768, 128]

    const int M = in_sizes[0];                     // 32768

    float *H, *Z, *W1T, *W2T;
    cudaGetSymbolAddress((void**)&H,   g_H);
    cudaGetSymbolAddress((void**)&Z,   g_Z);
    cudaGetSymbolAddress((void**)&W1T, g_w1t);
    cudaGetSymbolAddress((void**)&W2T, g_w2t);

    // transpose weights to [N,K]
    transpose_k<<<dim3(1024 / 32, 512 / 32), dim3(32, 8)>>>(w1, W1T, 512, 1024);
    transpose_k<<<dim3(128 / 32, 1024 / 32), dim3(32, 8)>>>(w2, W2T, 1024, 128);

    const int SMEM = 2 * STG_FL * (int)sizeof(float);   // 61440 B
    cudaFuncSetAttribute(mma_gemm<true>,
                         cudaFuncAttributeMaxDynamicSharedMemorySize, SMEM);
    cudaFuncSetAttribute(mma_gemm<false>,
                         cudaFuncAttributeMaxDynamicSharedMemorySize, SMEM);

    const int MB = M / BM;    // 128

    // L1: H = relu(gather(emb) @ conv_w^T + conv_b)      [M, 512]
    mma_gemm<true><<<dim3(512 / BN, MB), 256, SMEM>>>(
        emb, conv_w, conv_b, H, tokens, 512, 512, 1);

    // L2: Z = relu(H @ w1 + b1)                          [M, 1024]
    mma_gemm<false><<<dim3(1024 / BN, MB), 256, SMEM>>>(
        H, W1T, b1, Z, nullptr, 1024, 512, 1);

    // L3: out = Z @ w2 + b2                              [M, 128]
    mma_gemm<false><<<dim3(128 / BN, MB), 256, SMEM>>>(
        Z, W2T, b2, out, nullptr, 128, 1024, 0);
}

// round 5
// speedup vs baseline: 3.2864x; 1.1460x over previous
#include <cuda_runtime.h>
#include <cuda_bf16.h>
#include <cstdint>

// ---------------------------------------------------------------------------
// IntentSlotLabellingModel on GB300 (sm_103a), Round 4:
// TF32 mma.sync GEMM chain with cp.async 3-stage pipeline.
//   gather+cvt -> GEMM1+ReLU -> GEMM2+ReLU -> GEMM3+bias
//   M=32768, E=512, C=512, H=1024, L=128.
// All operands pre-converted to tf32 (pre-pass / prior epilogue), so the
// GEMM mainloop is pure LDGSTS.128 + LDS + HMMA. CTA 256x128, 8 warps,
// warp tile 64x64, BK=32, DEPTH=3.
// ---------------------------------------------------------------------------

#define BM 256
#define BN 128
#define BK 32
#define DEPTH 3
#define ASTR 36                         // padded row stride (floats)
#define A_ST (BM * ASTR)                // 9216 floats / stage
#define B_ST (BN * ASTR)                // 4608 floats / stage
#define STG  (A_ST + B_ST)              // 13824 floats / stage
#define SMEM_BYTES (DEPTH * STG * 4)    // 165888 B

__device__ float g_A[32768L * 512];     // gathered + tf32 embeddings
__device__ float g_H[32768L * 512];     // post-conv relu (tf32)
__device__ float g_Z[32768L * 1024];    // post-dec1 relu (tf32)
__device__ float g_cw[512L * 512];      // conv_w   tf32 [N,K]
__device__ float g_w1t[1024L * 512];    // dec_w1 -> tf32 [N,K]
__device__ float g_w2t[128L * 1024];    // dec_w2 -> tf32 [N,K]

__device__ __forceinline__ float f2tf32(float x) {
    uint32_t r;
    asm("cvt.rna.tf32.f32 %0, %1;" : "=r"(r) : "f"(x));
    return __uint_as_float(r);
}
__device__ __forceinline__ uint32_t smem_u32(const void* p) {
    uint32_t a;
    asm("{ .reg .u64 t; cvta.to.shared.u64 t, %1; cvt.u32.u64 %0, t; }"
        : "=r"(a) : "l"(p));
    return a;
}
__device__ __forceinline__ void cp_async16(uint32_t dst, const void* src) {
    asm volatile("cp.async.cg.shared.global [%0], [%1], 16;"
                 :: "r"(dst), "l"(src) : "memory");
}
__device__ __forceinline__ void cp_commit() {
    asm volatile("cp.async.commit_group;" ::: "memory");
}
template <int N> __device__ __forceinline__ void cp_wait() {
    asm volatile("cp.async.wait_group %0;" :: "n"(N) : "memory");
}
__device__ __forceinline__ void mma_tf32(float* d, const uint32_t* a, const uint32_t* b) {
    asm volatile(
        "mma.sync.aligned.m16n8k8.row.col.f32.tf32.tf32.f32 "
        "{%0,%1,%2,%3}, {%4,%5,%6,%7}, {%8,%9}, {%0,%1,%2,%3};"
        : "+f"(d[0]), "+f"(d[1]), "+f"(d[2]), "+f"(d[3])
        : "r"(a[0]), "r"(a[1]), "r"(a[2]), "r"(a[3]), "r"(b[0]), "r"(b[1]));
}

// ---------------------------------------------------------------------------
// GEMM: C[BM x BN tile] = A[M,K](tf32) @ B[N,K](tf32)^T + bias (relu/cvt opt)
// ---------------------------------------------------------------------------
__global__ void __launch_bounds__(256, 1)
mma_gemm(const float* __restrict__ A, const float* __restrict__ B,
         const float* __restrict__ bias, float* __restrict__ C,
         int N, int K, int relu_cvt)     // 1 => relu + tf32-cvt output
{
    extern __shared__ float smem[];
    const uint32_t sbase = smem_u32(smem);

    const int tid  = threadIdx.x;
    const int lane = tid & 31;
    const int warp = tid >> 5;
    const int warp_m = (warp >> 1) * 64;     // 0,64,128,192
    const int warp_n = (warp & 1) * 64;      // 0,64
    const int gr = lane >> 2;
    const int gc = lane & 3;

    const int  n0 = blockIdx.x * BN;
    const long m0 = (long)blockIdx.y * BM;

    // producer task setup: A 8 x cp16, B 4 x cp16 per thread
    const float* a_src[8]; uint32_t a_dst[8];
    #pragma unroll
    for (int i = 0; i < 8; i++) {
        int idx = tid + i * 256;             // 0..2047
        int r   = idx >> 3;                  // 0..255
        int c4  = (idx & 7) * 4;             // 0..28
        a_src[i] = A + (m0 + r) * (long)K + c4;
        a_dst[i] = sbase + (uint32_t)(r * ASTR + c4) * 4u;
    }
    const float* b_src[4]; uint32_t b_dst[4];
    #pragma unroll
    for (int i = 0; i < 4; i++) {
        int idx = tid + i * 256;             // 0..1023
        int r   = idx >> 3;                  // 0..127
        int c4  = (idx & 7) * 4;
        b_src[i] = B + (long)(n0 + r) * (long)K + c4;
        b_dst[i] = sbase + (uint32_t)(A_ST + r * ASTR + c4) * 4u;
    }

    const int S = K / BK;

    auto issue = [&](int s) {
        const uint32_t so = (uint32_t)((s % DEPTH) * STG * 4);
        const int k0 = s * BK;
        #pragma unroll
        for (int i = 0; i < 8; i++)
            cp_async16(a_dst[i] + so, a_src[i] + k0);
        #pragma unroll
        for (int i = 0; i < 4; i++)
            cp_async16(b_dst[i] + so, b_src[i] + k0);
    };

    issue(0); cp_commit();
    issue(1); cp_commit();

    float acc[4][8][4];
    #pragma unroll
    for (int mt = 0; mt < 4; mt++)
        #pragma unroll
        for (int nt = 0; nt < 8; nt++)
            #pragma unroll
            for (int r = 0; r < 4; r++)
                acc[mt][nt][r] = 0.0f;

    for (int s = 0; s < S; s++) {
        cp_wait<DEPTH - 2>();
        __syncthreads();
        if (s + 2 < S) issue(s + 2);
        cp_commit();

        const float* As = smem + (s % DEPTH) * STG;
        const float* Bs = As + A_ST;

        #pragma unroll
        for (int ks = 0; ks < BK; ks += 8) {
            uint32_t af[4][4], bf[8][2];
            #pragma unroll
            for (int mt = 0; mt < 4; mt++) {
                int r = (warp_m + mt * 16 + gr) * ASTR + ks + gc;
                af[mt][0] = __float_as_uint(As[r]);
                af[mt][1] = __float_as_uint(As[r + 8 * ASTR]);
                af[mt][2] = __float_as_uint(As[r + 4]);
                af[mt][3] = __float_as_uint(As[r + 8 * ASTR + 4]);
            }
            #pragma unroll
            for (int nt = 0; nt < 8; nt++) {
                int r = (warp_n + nt * 8 + gr) * ASTR + ks + gc;
                bf[nt][0] = __float_as_uint(Bs[r]);
                bf[nt][1] = __float_as_uint(Bs[r + 4]);
            }
            #pragma unroll
            for (int mt = 0; mt < 4; mt++)
                #pragma unroll
                for (int nt = 0; nt < 8; nt++)
                    mma_tf32(acc[mt][nt], af[mt], bf[nt]);
        }
    }

    // ---- epilogue ----
    #pragma unroll
    for (int nt = 0; nt < 8; nt++) {
        int n = n0 + warp_n + nt * 8 + gc * 2;
        float bb0 = bias[n], bb1 = bias[n + 1];
        #pragma unroll
        for (int mt = 0; mt < 4; mt++) {
            long m = m0 + warp_m + mt * 16 + gr;
            float2 v0, v1;
            v0.x = acc[mt][nt][0] + bb0;  v0.y = acc[mt][nt][1] + bb1;
            v1.x = acc[mt][nt][2] + bb0;  v1.y = acc[mt][nt][3] + bb1;
            if (relu_cvt) {
                v0.x = f2tf32(fmaxf(v0.x, 0.0f));
                v0.y = f2tf32(fmaxf(v0.y, 0.0f));
                v1.x = f2tf32(fmaxf(v1.x, 0.0f));
                v1.y = f2tf32(fmaxf(v1.y, 0.0f));
            }
            *reinterpret_cast<float2*>(C + m * (long)N + n)       = v0;
            *reinterpret_cast<float2*>(C + (m + 8) * (long)N + n) = v1;
        }
    }
}

// ---------------------------------------------------------------------------
// Pre-pass kernels
// ---------------------------------------------------------------------------
// gather embedding rows + convert to tf32: out[m, :] = tf32(emb[tok[m], :])
__global__ void gather_cvt(const float* __restrict__ emb,
                           const int* __restrict__ tok,
                           float* __restrict__ out)
{
    long i = (long)blockIdx.x * blockDim.x + threadIdx.x;   // float4 index
    int m = (int)(i >> 7);                                  // 128 float4 / row
    int c = (int)(i & 127) * 4;
    const float4 v = *reinterpret_cast<const float4*>(
        emb + (long)tok[m] * 512 + c);
    float4 t;
    t.x = f2tf32(v.x); t.y = f2tf32(v.y);
    t.z = f2tf32(v.z); t.w = f2tf32(v.w);
    *reinterpret_cast<float4*>(out + (long)m * 512 + c) = t;
}

// plain elementwise tf32 convert (conv_w, already [N,K])
__global__ void cvt_copy(const float* __restrict__ in, float* __restrict__ out)
{
    long i = ((long)blockIdx.x * blockDim.x + threadIdx.x) * 4;
    const float4 v = *reinterpret_cast<const float4*>(in + i);
    float4 t;
    t.x = f2tf32(v.x); t.y = f2tf32(v.y);
    t.z = f2tf32(v.z); t.w = f2tf32(v.w);
    *reinterpret_cast<float4*>(out + i) = t;
}

// transpose [K,N] -> [N,K] with tf32 convert
__global__ void transpose_cvt(const float* __restrict__ in, float* __restrict__ out,
                              int K, int N)
{
    __shared__ float t[32][33];
    int n0 = blockIdx.x * 32, k0 = blockIdx.y * 32;
    int x = threadIdx.x, y = threadIdx.y;
    #pragma unroll
    for (int i = 0; i < 32; i += 8)
        t[y + i][x] = in[(long)(k0 + y + i) * N + n0 + x];
    __syncthreads();
    #pragma unroll
    for (int i = 0; i < 32; i += 8)
        out[(long)(n0 + y + i) * K + k0 + x] = f2tf32(t[x][y + i]);
}

extern "C" void kernel_launch(void* const* d_in, const int* in_sizes, int n_in,
                              void* d_out, int out_size)
{
    const int*   tokens = (const int*)  d_in[0];   // [32768]
    const float* emb    = (const float*)d_in[1];   // [VOCAB, 512]
    const float* conv_w = (const float*)d_in[2];   // [512, 512]  (N,K)
    const float* conv_b = (const float*)d_in[3];   // [512]
    const float* w1     = (const float*)d_in[4];   // [512, 1024] (K,N)
    const float* b1     = (const float*)d_in[5];   // [1024]
    const float* w2     = (const float*)d_in[6];   // [1024, 128] (K,N)
    const float* b2     = (const float*)d_in[7];   // [128]
    float* out = (float*)d_out;                    // [32768, 128]

    const int M = in_sizes[0];                     // 32768

    float *A, *H, *Z, *CW, *W1T, *W2T;
    cudaGetSymbolAddress((void**)&A,   g_A);
    cudaGetSymbolAddress((void**)&H,   g_H);
    cudaGetSymbolAddress((void**)&Z,   g_Z);
    cudaGetSymbolAddress((void**)&CW,  g_cw);
    cudaGetSymbolAddress((void**)&W1T, g_w1t);
    cudaGetSymbolAddress((void**)&W2T, g_w2t);

    // pre-passes (weights tiny; gather ~64MB rw)
    gather_cvt<<<(int)((long)M * 128 / 256), 256>>>(emb, tokens, A);
    cvt_copy<<<512 * 512 / 4 / 256, 256>>>(conv_w, CW);
    transpose_cvt<<<dim3(1024 / 32, 512 / 32), dim3(32, 8)>>>(w1, W1T, 512, 1024);
    transpose_cvt<<<dim3(128 / 32, 1024 / 32), dim3(32, 8)>>>(w2, W2T, 1024, 128);

    cudaFuncSetAttribute(mma_gemm,
                         cudaFuncAttributeMaxDynamicSharedMemorySize, SMEM_BYTES);

    const int MB = M / BM;    // 128

    // L1: H = tf32(relu(A @ CW^T + conv_b))             [M, 512]
    mma_gemm<<<dim3(512 / BN, MB), 256, SMEM_BYTES>>>(A, CW, conv_b, H, 512, 512, 1);

    // L2: Z = tf32(relu(H @ W1T^T + b1))                [M, 1024]
    mma_gemm<<<dim3(1024 / BN, MB), 256, SMEM_BYTES>>>(H, W1T, b1, Z, 1024, 512, 1);

    // L3: out = Z @ W2T^T + b2                          [M, 128]
    mma_gemm<<<dim3(128 / BN, MB), 256, SMEM_BYTES>>>(Z, W2T, b2, out, 128, 1024, 0);
}

// round 6
// speedup vs baseline: 5.6041x; 1.7052x over previous
#include <cuda_runtime.h>
#include <cuda_fp16.h>
#include <cstdint>

// ---------------------------------------------------------------------------
// IntentSlotLabellingModel on GB300 (sm_103a), Round 5:
// FP16 mma.sync.m16n8k16 GEMM chain (fp32 accumulate) with cp.async pipeline.
//   gather+cvt -> GEMM1+ReLU -> GEMM2+ReLU -> GEMM3+bias
//   M=32768, E=512, C=512, H=1024, L=128.
// fp16 mantissa (10b) == tf32 mantissa -> same ~5e-4 rel err, 2x FLOP rate,
// half the operand bytes. CTA 256x128, 8 warps, warp tile 64x64, BK=64,
// DEPTH=3 cp.async ring. All operands pre-converted to half.
// ---------------------------------------------------------------------------

#define BM 256
#define BN 128
#define BK 64
#define DEPTH 3
#define SSTR_H 72                       // padded row stride in halves (144 B)
#define A_STH (BM * SSTR_H)             // 18432 halves / stage
#define B_STH (BN * SSTR_H)             // 9216 halves / stage
#define STG_H (A_STH + B_STH)           // 27648 halves / stage
#define SMEM_BYTES (DEPTH * STG_H * 2)  // 165888 B

__device__ __half g_A[32768L * 512];    // gathered fp16 embeddings
__device__ __half g_H[32768L * 512];    // post-conv relu (fp16)
__device__ __half g_Z[32768L * 1024];   // post-dec1 relu (fp16)
__device__ __half g_cw[512L * 512];     // conv_w  fp16 [N,K]
__device__ __half g_w1t[1024L * 512];   // dec_w1 -> fp16 [N,K]
__device__ __half g_w2t[128L * 1024];   // dec_w2 -> fp16 [N,K]

__device__ __forceinline__ uint32_t smem_u32(const void* p) {
    uint32_t a;
    asm("{ .reg .u64 t; cvta.to.shared.u64 t, %1; cvt.u32.u64 %0, t; }"
        : "=r"(a) : "l"(p));
    return a;
}
__device__ __forceinline__ void cp_async16(uint32_t dst, const void* src) {
    asm volatile("cp.async.cg.shared.global [%0], [%1], 16;"
                 :: "r"(dst), "l"(src) : "memory");
}
__device__ __forceinline__ void cp_commit() {
    asm volatile("cp.async.commit_group;" ::: "memory");
}
template <int N> __device__ __forceinline__ void cp_wait() {
    asm volatile("cp.async.wait_group %0;" :: "n"(N) : "memory");
}
__device__ __forceinline__ void mma_f16(float* d, const uint32_t* a, const uint32_t* b) {
    asm volatile(
        "mma.sync.aligned.m16n8k16.row.col.f32.f16.f16.f32 "
        "{%0,%1,%2,%3}, {%4,%5,%6,%7}, {%8,%9}, {%0,%1,%2,%3};"
        : "+f"(d[0]), "+f"(d[1]), "+f"(d[2]), "+f"(d[3])
        : "r"(a[0]), "r"(a[1]), "r"(a[2]), "r"(a[3]), "r"(b[0]), "r"(b[1]));
}

// ---------------------------------------------------------------------------
// GEMM: C[BM x BN tile] = A[M,K](f16) @ B[N,K](f16)^T + bias
// HALF_OUT: relu + store half (intermediate layers); else plain float out.
// ---------------------------------------------------------------------------
template <bool HALF_OUT>
__global__ void __launch_bounds__(256, 1)
mma_gemm(const __half* __restrict__ A, const __half* __restrict__ B,
         const float* __restrict__ bias, void* __restrict__ Cv,
         int N, int K)
{
    extern __shared__ __half smem[];
    const uint32_t sbase = smem_u32(smem);

    const int tid  = threadIdx.x;
    const int lane = tid & 31;
    const int warp = tid >> 5;
    const int warp_m = (warp >> 1) * 64;     // 0,64,128,192
    const int warp_n = (warp & 1) * 64;      // 0,64
    const int gr = lane >> 2;                // 0..7
    const int gc = lane & 3;                 // 0..3

    const int  n0 = blockIdx.x * BN;
    const long m0 = (long)blockIdx.y * BM;

    // producer tasks: A 8 x cp16 (8 halves), B 4 x cp16 per thread
    const __half* a_src[8]; uint32_t a_dst[8];
    #pragma unroll
    for (int i = 0; i < 8; i++) {
        int idx = tid + i * 256;             // 0..2047
        int r   = idx >> 3;                  // 0..255
        int c8  = (idx & 7) * 8;             // 0..56 halves
        a_src[i] = A + (m0 + r) * (long)K + c8;
        a_dst[i] = sbase + (uint32_t)(r * SSTR_H + c8) * 2u;
    }
    const __half* b_src[4]; uint32_t b_dst[4];
    #pragma unroll
    for (int i = 0; i < 4; i++) {
        int idx = tid + i * 256;             // 0..1023
        int r   = idx >> 3;                  // 0..127
        int c8  = (idx & 7) * 8;
        b_src[i] = B + (long)(n0 + r) * (long)K + c8;
        b_dst[i] = sbase + (uint32_t)((A_STH + r * SSTR_H + c8)) * 2u;
    }

    const int S = K / BK;

    auto issue = [&](int s) {
        const uint32_t so = (uint32_t)((s % DEPTH) * STG_H * 2);
        const int k0 = s * BK;
        #pragma unroll
        for (int i = 0; i < 8; i++)
            cp_async16(a_dst[i] + so, a_src[i] + k0);
        #pragma unroll
        for (int i = 0; i < 4; i++)
            cp_async16(b_dst[i] + so, b_src[i] + k0);
    };

    issue(0); cp_commit();
    issue(1); cp_commit();

    float acc[4][8][4];
    #pragma unroll
    for (int mt = 0; mt < 4; mt++)
        #pragma unroll
        for (int nt = 0; nt < 8; nt++)
            #pragma unroll
            for (int r = 0; r < 4; r++)
                acc[mt][nt][r] = 0.0f;

    for (int s = 0; s < S; s++) {
        cp_wait<DEPTH - 2>();
        __syncthreads();
        if (s + 2 < S) issue(s + 2);
        cp_commit();

        const __half* As = smem + (s % DEPTH) * STG_H;
        const __half* Bs = As + A_STH;

        #pragma unroll
        for (int ks = 0; ks < BK; ks += 16) {
            uint32_t af[4][4], bf[8][2];
            #pragma unroll
            for (int mt = 0; mt < 4; mt++) {
                int r = (warp_m + mt * 16 + gr) * SSTR_H + ks + gc * 2;
                af[mt][0] = *reinterpret_cast<const uint32_t*>(&As[r]);
                af[mt][1] = *reinterpret_cast<const uint32_t*>(&As[r + 8 * SSTR_H]);
                af[mt][2] = *reinterpret_cast<const uint32_t*>(&As[r + 8]);
                af[mt][3] = *reinterpret_cast<const uint32_t*>(&As[r + 8 * SSTR_H + 8]);
            }
            #pragma unroll
            for (int nt = 0; nt < 8; nt++) {
                int r = (warp_n + nt * 8 + gr) * SSTR_H + ks + gc * 2;
                bf[nt][0] = *reinterpret_cast<const uint32_t*>(&Bs[r]);
                bf[nt][1] = *reinterpret_cast<const uint32_t*>(&Bs[r + 8]);
            }
            #pragma unroll
            for (int mt = 0; mt < 4; mt++)
                #pragma unroll
                for (int nt = 0; nt < 8; nt++)
                    mma_f16(acc[mt][nt], af[mt], bf[nt]);
        }
    }

    // ---- epilogue ----
    #pragma unroll
    for (int nt = 0; nt < 8; nt++) {
        int n = n0 + warp_n + nt * 8 + gc * 2;
        float bb0 = bias[n], bb1 = bias[n + 1];
        #pragma unroll
        for (int mt = 0; mt < 4; mt++) {
            long m = m0 + warp_m + mt * 16 + gr;
            float x0 = acc[mt][nt][0] + bb0, x1 = acc[mt][nt][1] + bb1;
            float x2 = acc[mt][nt][2] + bb0, x3 = acc[mt][nt][3] + bb1;
            if (HALF_OUT) {
                __half* C = (__half*)Cv;
                __half2 h0 = __floats2half2_rn(fmaxf(x0, 0.0f), fmaxf(x1, 0.0f));
                __half2 h1 = __floats2half2_rn(fmaxf(x2, 0.0f), fmaxf(x3, 0.0f));
                *reinterpret_cast<__half2*>(C + m * (long)N + n)       = h0;
                *reinterpret_cast<__half2*>(C + (m + 8) * (long)N + n) = h1;
            } else {
                float* C = (float*)Cv;
                *reinterpret_cast<float2*>(C + m * (long)N + n)       = make_float2(x0, x1);
                *reinterpret_cast<float2*>(C + (m + 8) * (long)N + n) = make_float2(x2, x3);
            }
        }
    }
}

// ---------------------------------------------------------------------------
// Pre-pass kernels (all tiny vs GEMMs)
// ---------------------------------------------------------------------------
// gather + fp16 convert: out[m,:] = half(emb[tok[m],:])
__global__ void gather_cvt(const float* __restrict__ emb,
                           const int* __restrict__ tok,
                           __half* __restrict__ out)
{
    long i = (long)blockIdx.x * blockDim.x + threadIdx.x;   // float4 index
    int m = (int)(i >> 7);                                  // 128 float4 / row
    int c = (int)(i & 127) * 4;
    const float4 v = *reinterpret_cast<const float4*>(emb + (long)tok[m] * 512 + c);
    __half2 h0 = __floats2half2_rn(v.x, v.y);
    __half2 h1 = __floats2half2_rn(v.z, v.w);
    *reinterpret_cast<__half2*>(out + (long)m * 512 + c)     = h0;
    *reinterpret_cast<__half2*>(out + (long)m * 512 + c + 2) = h1;
}

// elementwise fp16 convert (conv_w already [N,K])
__global__ void cvt_copy(const float* __restrict__ in, __half* __restrict__ out)
{
    long i = ((long)blockIdx.x * blockDim.x + threadIdx.x) * 4;
    const float4 v = *reinterpret_cast<const float4*>(in + i);
    *reinterpret_cast<__half2*>(out + i)     = __floats2half2_rn(v.x, v.y);
    *reinterpret_cast<__half2*>(out + i + 2) = __floats2half2_rn(v.z, v.w);
}

// transpose [K,N] -> [N,K] with fp16 convert
__global__ void transpose_cvt(const float* __restrict__ in, __half* __restrict__ out,
                              int K, int N)
{
    __shared__ float t[32][33];
    int n0 = blockIdx.x * 32, k0 = blockIdx.y * 32;
    int x = threadIdx.x, y = threadIdx.y;
    #pragma unroll
    for (int i = 0; i < 32; i += 8)
        t[y + i][x] = in[(long)(k0 + y + i) * N + n0 + x];
    __syncthreads();
    #pragma unroll
    for (int i = 0; i < 32; i += 8)
        out[(long)(n0 + y + i) * K + k0 + x] = __float2half_rn(t[x][y + i]);
}

extern "C" void kernel_launch(void* const* d_in, const int* in_sizes, int n_in,
                              void* d_out, int out_size)
{
    const int*   tokens = (const int*)  d_in[0];   // [32768]
    const float* emb    = (const float*)d_in[1];   // [VOCAB, 512]
    const float* conv_w = (const float*)d_in[2];   // [512, 512]  (N,K)
    const float* conv_b = (const float*)d_in[3];   // [512]
    const float* w1     = (const float*)d_in[4];   // [512, 1024] (K,N)
    const float* b1     = (const float*)d_in[5];   // [1024]
    const float* w2     = (const float*)d_in[6];   // [1024, 128] (K,N)
    const float* b2     = (const float*)d_in[7];   // [128]
    float* out = (float*)d_out;                    // [32768, 128]

    const int M = in_sizes[0];                     // 32768

    __half *A, *H, *Z, *CW, *W1T, *W2T;
    cudaGetSymbolAddress((void**)&A,   g_A);
    cudaGetSymbolAddress((void**)&H,   g_H);
    cudaGetSymbolAddress((void**)&Z,   g_Z);
    cudaGetSymbolAddress((void**)&CW,  g_cw);
    cudaGetSymbolAddress((void**)&W1T, g_w1t);
    cudaGetSymbolAddress((void**)&W2T, g_w2t);

    // pre-passes
    gather_cvt<<<(int)((long)M * 128 / 256), 256>>>(emb, tokens, A);
    cvt_copy<<<512 * 512 / 4 / 256, 256>>>(conv_w, CW);
    transpose_cvt<<<dim3(1024 / 32, 512 / 32), dim3(32, 8)>>>(w1, W1T, 512, 1024);
    transpose_cvt<<<dim3(128 / 32, 1024 / 32), dim3(32, 8)>>>(w2, W2T, 1024, 128);

    cudaFuncSetAttribute(mma_gemm<true>,
                         cudaFuncAttributeMaxDynamicSharedMemorySize, SMEM_BYTES);
    cudaFuncSetAttribute(mma_gemm<false>,
                         cudaFuncAttributeMaxDynamicSharedMemorySize, SMEM_BYTES);

    const int MB = M / BM;    // 128

    // L1: H = half(relu(A @ CW^T + conv_b))             [M, 512]
    mma_gemm<true><<<dim3(512 / BN, MB), 256, SMEM_BYTES>>>(A, CW, conv_b, H, 512, 512);

    // L2: Z = half(relu(H @ W1T^T + b1))                [M, 1024]
    mma_gemm<true><<<dim3(1024 / BN, MB), 256, SMEM_BYTES>>>(H, W1T, b1, Z, 1024, 512);

    // L3: out = Z @ W2T^T + b2                          [M, 128]
    mma_gemm<false><<<dim3(128 / BN, MB), 256, SMEM_BYTES>>>(Z, W2T, b2, out, 128, 1024);
}